// round 12
// baseline (speedup 1.0000x reference)
#include <cuda_runtime.h>
#include <cuda_bf16.h>
#include <math.h>
#include <stdint.h>

#define S 1024
#define D 1024
#define H 16
#define HD 64
#define NL 6
#define DFF 4096
#define EPS 1.1920929e-07f

typedef __nv_bfloat16 bf16;

// ================= device scratch (no allocations allowed) =================
__device__ float g_x [S*D];
__device__ float g_x0[S*D];
__device__ float g_xl[S*D];
__device__ float g_q [S*D];
__device__ float g_k [S*D];
__device__ float g_v [S*D];
__device__ float g_v1[S*D];
__device__ bf16  g_xnh[S*D],  g_xnl[S*D];
__device__ bf16  g_yh [S*D],  g_yl [S*D];
__device__ bf16  g_hh [S*DFF], g_hl [S*DFF];
__device__ bf16  g_qh[S*D], g_ql[S*D];
__device__ bf16  g_kh[S*D], g_kl[S*D];
__device__ bf16  g_vh[S*D], g_vl[S*D];
__device__ bf16  g_wqkvh[(size_t)NL*3*D*D], g_wqkvl[(size_t)NL*3*D*D];
__device__ bf16  g_woh  [(size_t)NL*D*D],   g_wol  [(size_t)NL*D*D];
__device__ bf16  g_wfch [(size_t)NL*DFF*D], g_wfcl [(size_t)NL*DFF*D];
__device__ bf16  g_wph  [(size_t)NL*D*DFF], g_wpl  [(size_t)NL*D*DFF];
__device__ unsigned char g_mask[S*S];
__device__ int   g_cpad[S+1];
__device__ float g_cos[S*32];
__device__ float g_sin[S*32];

// ================= helpers =================
#define SWZ(x) ((x) ^ (((x) >> 3) & 0x70))

__device__ __forceinline__ uint32_t smem_u32(const void* p) {
    return (uint32_t)__cvta_generic_to_shared((void*)p);
}
#define CP16(dst, src) asm volatile("cp.async.cg.shared.global [%0], [%1], 16;" :: "r"(dst), "l"(src) : "memory")
#define CP_COMMIT()    asm volatile("cp.async.commit_group;" ::: "memory")
#define CP_WAIT(n)     asm volatile("cp.async.wait_group %0;" :: "n"(n) : "memory")

__device__ __forceinline__ void ldsm4(uint32_t& a0, uint32_t& a1, uint32_t& a2, uint32_t& a3,
                                      uint32_t addr) {
    asm volatile("ldmatrix.sync.aligned.m8n8.x4.shared.b16 {%0,%1,%2,%3}, [%4];"
                 : "=r"(a0), "=r"(a1), "=r"(a2), "=r"(a3) : "r"(addr));
}
__device__ __forceinline__ void ldsm4t(uint32_t& a0, uint32_t& a1, uint32_t& a2, uint32_t& a3,
                                       uint32_t addr) {
    asm volatile("ldmatrix.sync.aligned.m8n8.x4.trans.shared.b16 {%0,%1,%2,%3}, [%4];"
                 : "=r"(a0), "=r"(a1), "=r"(a2), "=r"(a3) : "r"(addr));
}
__device__ __forceinline__ void mma16816(float* c, const uint32_t* a, const uint32_t* b) {
    asm volatile("mma.sync.aligned.m16n8k16.row.col.f32.bf16.bf16.f32 "
                 "{%0,%1,%2,%3}, {%4,%5,%6,%7}, {%8,%9}, {%0,%1,%2,%3};"
                 : "+f"(c[0]), "+f"(c[1]), "+f"(c[2]), "+f"(c[3])
                 : "r"(a[0]), "r"(a[1]), "r"(a[2]), "r"(a[3]), "r"(b[0]), "r"(b[1]));
}
__device__ __forceinline__ void split2(float v, bf16& h, bf16& l) {
    h = __float2bfloat16(v);
    l = __float2bfloat16(v - __bfloat162float(h));
}
__device__ __forceinline__ void pack_split(float a, float b, uint32_t& ph, uint32_t& pl) {
    bf16 ah, al, bh_, bl_;
    split2(a, ah, al); split2(b, bh_, bl_);
    __nv_bfloat162 vh2 = __halves2bfloat162(ah, bh_);
    __nv_bfloat162 vl2 = __halves2bfloat162(al, bl_);
    ph = *reinterpret_cast<uint32_t*>(&vh2);
    pl = *reinterpret_cast<uint32_t*>(&vl2);
}

// ================= setup kernels =================
__global__ void scan_kernel(const int* __restrict__ levels, int* __restrict__ cpad) {
    __shared__ int sh[S];
    int t = threadIdx.x;
    sh[t] = (levels[t] == 0) ? 1 : 0;
    __syncthreads();
    for (int off = 1; off < S; off <<= 1) {
        int add = (t >= off) ? sh[t - off] : 0;
        __syncthreads();
        sh[t] += add;
        __syncthreads();
    }
    cpad[t + 1] = sh[t];
    if (t == 0) cpad[0] = 0;
}

__global__ void mask_kernel(const int* __restrict__ levels, const int* __restrict__ sidx,
                            const int* __restrict__ cpad, unsigned char* __restrict__ mk) {
    int idx = blockIdx.x * 256 + threadIdx.x;
    int i = idx >> 10, j = idx & 1023;
    bool causal = (i >= j);
    bool same   = (sidx[i] == sidx[j]);
    int  cnt    = cpad[i] - cpad[j + 1];
    bool markov = (levels[j] == 0) && (cnt > 0);
    mk[idx] = (causal && same && !markov) ? 1 : 0;
}

__global__ void ropetab_kernel(float* __restrict__ ct, float* __restrict__ st) {
    int t = blockIdx.x, l = threadIdx.x;
    double inv = pow(10000.0, -(double)(2 * l) / (double)HD);
    double fr  = (double)t * inv;
    ct[t * 32 + l] = (float)cos(fr);
    st[t * 32 + l] = (float)sin(fr);
}

__global__ __launch_bounds__(256) void split_kernel(const float* __restrict__ src,
                                                    bf16* __restrict__ h, bf16* __restrict__ l,
                                                    int lg2, size_t dstStride) {
    size_t idx = (size_t)blockIdx.x * 256 + threadIdx.x;
    size_t e = idx << 2;
    int layer = (int)(e >> lg2);
    size_t off = e & (((size_t)1 << lg2) - 1);
    size_t dpos = (size_t)layer * dstStride + off;
    float4 v = *(const float4*)(src + e);
    bf16 h0, h1, h2, h3, l0, l1, l2, l3;
    split2(v.x, h0, l0); split2(v.y, h1, l1); split2(v.z, h2, l2); split2(v.w, h3, l3);
    *(__nv_bfloat162*)(h + dpos)     = __halves2bfloat162(h0, h1);
    *(__nv_bfloat162*)(h + dpos + 2) = __halves2bfloat162(h2, h3);
    *(__nv_bfloat162*)(l + dpos)     = __halves2bfloat162(l0, l1);
    *(__nv_bfloat162*)(l + dpos + 2) = __halves2bfloat162(l2, l3);
}

// ================= rms / prelayer (float4, register-resident) =================
__device__ __forceinline__ float blk_reduce(float s, float* red, int tid) {
    #pragma unroll
    for (int o = 16; o; o >>= 1) s += __shfl_xor_sync(0xffffffffu, s, o);
    if ((tid & 31) == 0) red[tid >> 5] = s;
    __syncthreads();
    if (tid == 0) {
        float t2 = 0.f;
        #pragma unroll
        for (int w = 0; w < 8; w++) t2 += red[w];
        red[0] = t2;
    }
    __syncthreads();
    return red[0];
}

__global__ __launch_bounds__(256) void rms_dual_kernel(const float* __restrict__ in,
                                                       float* __restrict__ out1,
                                                       float* __restrict__ out2) {
    __shared__ float red[8];
    int row = blockIdx.x, tid = threadIdx.x;
    float4 v = ((const float4*)(in + (size_t)row * D))[tid];
    float ss = blk_reduce(v.x*v.x + v.y*v.y + v.z*v.z + v.w*v.w, red, tid);
    float sc = rsqrtf(ss * (1.0f / D) + EPS);
    v.x *= sc; v.y *= sc; v.z *= sc; v.w *= sc;
    ((float4*)(out1 + (size_t)row * D))[tid] = v;
    if (out2) ((float4*)(out2 + (size_t)row * D))[tid] = v;
}

__global__ __launch_bounds__(256) void rms_split_kernel(const float* __restrict__ in,
                                                        bf16* __restrict__ oh, bf16* __restrict__ ol) {
    __shared__ float red[8];
    int row = blockIdx.x, tid = threadIdx.x;
    float4 v = ((const float4*)(in + (size_t)row * D))[tid];
    float ss = blk_reduce(v.x*v.x + v.y*v.y + v.z*v.z + v.w*v.w, red, tid);
    float sc = rsqrtf(ss * (1.0f / D) + EPS);
    bf16 h0,h1,h2,h3,l0,l1,l2,l3;
    split2(v.x*sc,h0,l0); split2(v.y*sc,h1,l1); split2(v.z*sc,h2,l2); split2(v.w*sc,h3,l3);
    size_t p = (size_t)row * D + tid * 4;
    *(__nv_bfloat162*)(oh+p)   = __halves2bfloat162(h0,h1);
    *(__nv_bfloat162*)(oh+p+2) = __halves2bfloat162(h2,h3);
    *(__nv_bfloat162*)(ol+p)   = __halves2bfloat162(l0,l1);
    *(__nv_bfloat162*)(ol+p+2) = __halves2bfloat162(l2,l3);
}

__global__ __launch_bounds__(256) void prelayer_kernel(const float* __restrict__ x,
                                                       const float* __restrict__ x0,
                                                       const float* __restrict__ lambdas, int layer,
                                                       float* __restrict__ xl,
                                                       bf16* __restrict__ oh, bf16* __restrict__ ol) {
    __shared__ float red[8];
    int row = blockIdx.x, tid = threadIdx.x;
    float la = lambdas[2 * layer], lb = lambdas[2 * layer + 1];
    float4 a = ((const float4*)(x  + (size_t)row * D))[tid];
    float4 b = ((const float4*)(x0 + (size_t)row * D))[tid];
    float4 v = make_float4(la*a.x + lb*b.x, la*a.y + lb*b.y, la*a.z + lb*b.z, la*a.w + lb*b.w);
    ((float4*)(xl + (size_t)row * D))[tid] = v;
    float ss = blk_reduce(v.x*v.x + v.y*v.y + v.z*v.z + v.w*v.w, red, tid);
    float sc = rsqrtf(ss * (1.0f / D) + EPS);
    bf16 h0,h1,h2,h3,l0,l1,l2,l3;
    split2(v.x*sc,h0,l0); split2(v.y*sc,h1,l1); split2(v.z*sc,h2,l2); split2(v.w*sc,h3,l3);
    size_t p = (size_t)row * D + tid * 4;
    *(__nv_bfloat162*)(oh+p)   = __halves2bfloat162(h0,h1);
    *(__nv_bfloat162*)(oh+p+2) = __halves2bfloat162(h2,h3);
    *(__nv_bfloat162*)(ol+p)   = __halves2bfloat162(l0,l1);
    *(__nv_bfloat162*)(ol+p+2) = __halves2bfloat162(l2,l3);
}

// ================= mma.sync split-bf16 GEMM: 3-stage, load-before-compute =================
// C[128 x BN tile] = (Ah+Al)[M,K] @ (Bh+Bl)[N,K]^T    (3-term split)
// EPI 0: QKV fp32 de-concat (ld 1024); EPI 1: C0 = Res + acc; EPI 2: split(relu(acc)^2)
template <int BN, int EPI>
__global__ __launch_bounds__(256) void mma_gemm(
    const bf16* __restrict__ Ah, const bf16* __restrict__ Al,
    const bf16* __restrict__ Bh, const bf16* __restrict__ Bl,
    float* __restrict__ C0, float* __restrict__ C1, float* __restrict__ C2,
    const float* __restrict__ Res, bf16* __restrict__ Hh, bf16* __restrict__ Hl,
    int K, int ldC)
{
    constexpr int WM = (BN == 128) ? 2 : 4;    // warp grid rows
    constexpr int WN = 8 / WM;                 // warp grid cols
    constexpr int MI = 128 / (WM * 16);        // m16 tiles per warp
    constexpr int NJ = BN / (WN * 8);          // n8 tiles per warp
    constexpr int RW = 128 / WM;               // rows per warp
    constexpr int CW = BN / WN;                // cols per warp
    constexpr int BSTRIDE = BN * 128;
    constexpr int STAGE = 32768 + 2 * BSTRIDE;
    extern __shared__ char smem[];
    const uint32_t sb = smem_u32(smem);
    const int tid  = threadIdx.x;
    const int warp = tid >> 5, lane = tid & 31;
    const int wm = warp % WM, wn = warp / WM;
    const int row0 = blockIdx.y * 128, col0 = blockIdx.x * BN;

    auto load_chunk = [&](int st, int c) {
        uint32_t tb = sb + st * STAGE;
        int k0 = c << 6;
        #pragma unroll
        for (int i = tid; i < 1024; i += 256) {
            int r = i >> 3, e = (i & 7) << 3;
            uint32_t so = SWZ((uint32_t)(r << 7) + (e << 1));
            size_t ga = (size_t)(row0 + r) * K + k0 + e;
            CP16(tb + so,         Ah + ga);
            CP16(tb + 16384 + so, Al + ga);
        }
        #pragma unroll
        for (int i = tid; i < BN * 8; i += 256) {
            int r = i >> 3, e = (i & 7) << 3;
            uint32_t so = SWZ((uint32_t)(r << 7) + (e << 1));
            size_t gb = (size_t)(col0 + r) * K + k0 + e;
            CP16(tb + 32768 + so,           Bh + gb);
            CP16(tb + 32768 + BSTRIDE + so, Bl + gb);
        }
        CP_COMMIT();
    };

    float acc[MI][NJ][4];
    #pragma unroll
    for (int i = 0; i < MI; i++)
        #pragma unroll
        for (int j = 0; j < NJ; j++)
            #pragma unroll
            for (int r = 0; r < 4; r++) acc[i][j][r] = 0.f;

    load_chunk(0, 0);
    load_chunk(1, 1);

    const int NC = K >> 6;
    const int lrow = lane & 15;
    const uint32_t lk = (uint32_t)(lane >> 4) << 4;

    for (int c = 0; c < NC; c++) {
        const int st = c % 3;
        if (c + 1 < NC) { CP_WAIT(1); } else { CP_WAIT(0); }
        __syncthreads();
        if (c + 2 < NC) load_chunk((c + 2) % 3, c + 2);   // issue early, overlap with compute
        const uint32_t aB = sb + st * STAGE;
        const uint32_t bB = aB + 32768;
        #pragma unroll
        for (int ks = 0; ks < 4; ks++) {
            uint32_t ah[MI][4], al[MI][4], bh[NJ][2], bl[NJ][2];
            #pragma unroll
            for (int i = 0; i < MI; i++) {
                int r = wm * RW + i * 16 + lrow;
                uint32_t off = SWZ((uint32_t)(r << 7) + (uint32_t)(ks << 5) + lk);
                ldsm4(ah[i][0], ah[i][1], ah[i][2], ah[i][3], aB + off);
                ldsm4(al[i][0], al[i][1], al[i][2], al[i][3], aB + 16384 + off);
            }
            #pragma unroll
            for (int jp = 0; jp < NJ / 2; jp++) {
                int r = wn * CW + jp * 16 + lrow;
                uint32_t off = SWZ((uint32_t)(r << 7) + (uint32_t)(ks << 5) + lk);
                uint32_t t0, t1, t2, t3;
                ldsm4(t0, t1, t2, t3, bB + off);
                bh[2*jp][0] = t0; bh[2*jp][1] = t2;
                bh[2*jp+1][0] = t1; bh[2*jp+1][1] = t3;
                ldsm4(t0, t1, t2, t3, bB + BSTRIDE + off);
                bl[2*jp][0] = t0; bl[2*jp][1] = t2;
                bl[2*jp+1][0] = t1; bl[2*jp+1][1] = t3;
            }
            #pragma unroll
            for (int i = 0; i < MI; i++)
                #pragma unroll
                for (int j = 0; j < NJ; j++) {
                    mma16816(acc[i][j], ah[i], bh[j]);
                    mma16816(acc[i][j], ah[i], bl[j]);
                    mma16816(acc[i][j], al[i], bh[j]);
                }
        }
    }

    const int rbase = row0 + wm * RW + (lane >> 2);
    const int cwarp = wn * CW + (lane & 3) * 2;

    if (EPI == 0) {
        float* C = C0; int cg0 = col0;
        if (col0 >= 2048)      { C = C2; cg0 = col0 - 2048; }
        else if (col0 >= 1024) { C = C1; cg0 = col0 - 1024; }
        #pragma unroll
        for (int i = 0; i < MI; i++)
            #pragma unroll
            for (int j = 0; j < NJ; j++) {
                int cc = cg0 + cwarp + j * 8;
                *(float2*)(C + (size_t)(rbase + i * 16)     * 1024 + cc) = make_float2(acc[i][j][0], acc[i][j][1]);
                *(float2*)(C + (size_t)(rbase + i * 16 + 8) * 1024 + cc) = make_float2(acc[i][j][2], acc[i][j][3]);
            }
    } else if (EPI == 1) {
        #pragma unroll
        for (int i = 0; i < MI; i++)
            #pragma unroll
            for (int j = 0; j < NJ; j++) {
                int cc = col0 + cwarp + j * 8;
                #pragma unroll
                for (int hh2 = 0; hh2 < 2; hh2++) {
                    size_t off = (size_t)(rbase + i * 16 + hh2 * 8) * ldC + cc;
                    float2 rv = *(const float2*)(Res + off);
                    *(float2*)(C0 + off) = make_float2(acc[i][j][2*hh2] + rv.x,
                                                       acc[i][j][2*hh2+1] + rv.y);
                }
            }
    } else {
        #pragma unroll
        for (int i = 0; i < MI; i++)
            #pragma unroll
            for (int j = 0; j < NJ; j++) {
                int cc = col0 + cwarp + j * 8;
                #pragma unroll
                for (int hh2 = 0; hh2 < 2; hh2++) {
                    size_t off = (size_t)(rbase + i * 16 + hh2 * 8) * ldC + cc;
                    float p0 = fmaxf(acc[i][j][2*hh2],   0.f); p0 *= p0;
                    float p1 = fmaxf(acc[i][j][2*hh2+1], 0.f); p1 *= p1;
                    bf16 h0, h1, l0, l1;
                    split2(p0, h0, l0); split2(p1, h1, l1);
                    *(__nv_bfloat162*)(Hh + off) = __halves2bfloat162(h0, h1);
                    *(__nv_bfloat162*)(Hl + off) = __halves2bfloat162(l0, l1);
                }
            }
    }
}

// ================= qkvprep: per-head rms + rope + vmix -> split bf16 =================
__global__ __launch_bounds__(128) void qkvprep_kernel(
    const float* __restrict__ Q, const float* __restrict__ Kt, const float* __restrict__ V,
    float* __restrict__ V1, const float* __restrict__ lamb, int layer,
    const float* __restrict__ ctab, const float* __restrict__ stab,
    bf16* __restrict__ qh, bf16* __restrict__ ql,
    bf16* __restrict__ kh, bf16* __restrict__ kl,
    bf16* __restrict__ vh, bf16* __restrict__ vl)
{
    int t = blockIdx.x;
    int h = blockIdx.y * 4 + (threadIdx.x >> 5);
    int lane = threadIdx.x & 31;
    int base = t * D + h * HD;
    float c  = ctab[t * 32 + lane];
    float sn = stab[t * 32 + lane];
    bf16 hh, ll;

    float a = Q[base + lane], b = Q[base + 32 + lane];
    float s = a * a + b * b;
    #pragma unroll
    for (int o = 16; o; o >>= 1) s += __shfl_xor_sync(0xffffffffu, s, o);
    float r = rsqrtf(s * (1.0f / HD) + EPS);
    a *= r; b *= r;
    float ra = ( a * c + b * sn) * 0.125f;
    float rb = (-a * sn + b * c) * 0.125f;
    split2(ra, hh, ll); qh[base + lane] = hh;      ql[base + lane] = ll;
    split2(rb, hh, ll); qh[base + 32 + lane] = hh; ql[base + 32 + lane] = ll;

    a = Kt[base + lane]; b = Kt[base + 32 + lane];
    s = a * a + b * b;
    #pragma unroll
    for (int o = 16; o; o >>= 1) s += __shfl_xor_sync(0xffffffffu, s, o);
    r = rsqrtf(s * (1.0f / HD) + EPS);
    a *= r; b *= r;
    ra =  a * c + b * sn;
    rb = -a * sn + b * c;
    split2(ra, hh, ll); kh[base + lane] = hh;      kl[base + lane] = ll;
    split2(rb, hh, ll); kh[base + 32 + lane] = hh; kl[base + 32 + lane] = ll;

    float lm = lamb[layer];
    float v0 = V[base + lane], v1 = V[base + 32 + lane];
    if (layer == 0) { V1[base + lane] = v0; V1[base + 32 + lane] = v1; }
    float w0 = V1[base + lane], w1 = V1[base + 32 + lane];
    v0 = (1.f - lm) * v0 + lm * w0;
    v1 = (1.f - lm) * v1 + lm * w1;
    split2(v0, hh, ll); vh[base + lane] = hh;      vl[base + lane] = ll;
    split2(v1, hh, ll); vh[base + 32 + lane] = hh; vl[base + 32 + lane] = ll;
}

// ================= tensor-core flash attention (split bf16, 3-stage) =================
__global__ __launch_bounds__(128) void attn_mma_kernel(
    const bf16* __restrict__ Qh, const bf16* __restrict__ Ql,
    const bf16* __restrict__ Kh, const bf16* __restrict__ Kl,
    const bf16* __restrict__ Vh, const bf16* __restrict__ Vl,
    bf16* __restrict__ Yh, bf16* __restrict__ Yl,
    const unsigned char* __restrict__ mk)
{
    extern __shared__ __align__(128) char sm[];
    const int h  = blockIdx.y;
    const int qb = gridDim.x - 1 - blockIdx.x;   // heavy blocks first
    const int q0 = qb * 64;
    const int tid = threadIdx.x, warp = tid >> 5, lane = tid & 31;
    const uint32_t sb = smem_u32(sm);
    const int NT = qb + 1;

    for (int i = tid; i < 512; i += 128) {
        int r = i >> 3, e = (i & 7) << 3;
        uint32_t so = SWZ((uint32_t)(r << 7) + (e << 1));
        size_t g = (size_t)(q0 + r) * D + h * 64 + e;
        CP16(sb + so,        Qh + g);
        CP16(sb + 8192 + so, Ql + g);
    }
    CP_COMMIT();

    auto load_stage = [&](int st, int kt) {
        uint32_t tb = sb + 16384 + st * 36864;
        int k0 = kt * 64;
        for (int i = tid; i < 512; i += 128) {
            int r = i >> 3, e = (i & 7) << 3;
            uint32_t so = SWZ((uint32_t)(r << 7) + (e << 1));
            size_t g = (size_t)(k0 + r) * D + h * 64 + e;
            CP16(tb + so,         Kh + g);
            CP16(tb + 8192 + so,  Kl + g);
            CP16(tb + 16384 + so, Vh + g);
            CP16(tb + 24576 + so, Vl + g);
        }
        for (int i = tid; i < 256; i += 128) {
            int r = i >> 2, e = (i & 3) << 4;
            CP16(tb + 32768 + (r << 6) + e, mk + (size_t)(q0 + r) * S + k0 + e);
        }
        CP_COMMIT();
    };
    load_stage(0, 0);
    if (NT > 1) load_stage(1, 1);

    float m0 = -1e30f, m1 = -1e30f, l0 = 0.f, l1 = 0.f;
    float o[8][4] = {};
    const int r4 = lane >> 2;
    const int cq = (lane & 3) << 1;
    const int lrow = lane & 15;
    const uint32_t lkb = (uint32_t)(lane >> 4) << 4;

    for (int kt = 0; kt < NT; kt++) {
        const int st = kt % 3;
        if (kt + 1 < NT) { CP_WAIT(1); } else { CP_WAIT(0); }
        __syncthreads();
        if (kt + 2 < NT) load_stage((kt + 2) % 3, kt + 2);   // overlap with compute
        const uint32_t tb = sb + 16384 + st * 36864;
        const char* mbase = sm + 16384 + st * 36864 + 32768;

        // ---- S = Q K^T ----
        float sa[8][4] = {};
        #pragma unroll
        for (int ks = 0; ks < 4; ks++) {
            uint32_t qah[4], qal[4];
            {
                uint32_t off = SWZ((uint32_t)((warp * 16 + lrow) << 7) + (uint32_t)(ks << 5) + lkb);
                ldsm4(qah[0], qah[1], qah[2], qah[3], sb + off);
                ldsm4(qal[0], qal[1], qal[2], qal[3], sb + 8192 + off);
            }
            uint32_t bh[8][2], bl[8][2];
            #pragma unroll
            for (int jp = 0; jp < 4; jp++) {
                uint32_t off = SWZ((uint32_t)((jp * 16 + lrow) << 7) + (uint32_t)(ks << 5) + lkb);
                uint32_t t0, t1, t2, t3;
                ldsm4(t0, t1, t2, t3, tb + off);
                bh[2*jp][0]=t0; bh[2*jp][1]=t2; bh[2*jp+1][0]=t1; bh[2*jp+1][1]=t3;
                ldsm4(t0, t1, t2, t3, tb + 8192 + off);
                bl[2*jp][0]=t0; bl[2*jp][1]=t2; bl[2*jp+1][0]=t1; bl[2*jp+1][1]=t3;
            }
            #pragma unroll
            for (int j = 0; j < 8; j++) {
                mma16816(sa[j], qah, bh[j]);
                mma16816(sa[j], qah, bl[j]);
                mma16816(sa[j], qal, bh[j]);
            }
        }

        // ---- mask ----
        #pragma unroll
        for (int j = 0; j < 8; j++) {
            int c0 = j * 8 + cq;
            unsigned short mw0 = *(const unsigned short*)(mbase + ((warp*16 + r4)     << 6) + c0);
            unsigned short mw1 = *(const unsigned short*)(mbase + ((warp*16 + r4 + 8) << 6) + c0);
            sa[j][0] = (mw0 & 0xff) ? sa[j][0] : -1e30f;
            sa[j][1] = (mw0 >> 8)   ? sa[j][1] : -1e30f;
            sa[j][2] = (mw1 & 0xff) ? sa[j][2] : -1e30f;
            sa[j][3] = (mw1 >> 8)   ? sa[j][3] : -1e30f;
        }

        // ---- online softmax ----
        float tm0 = -1e30f, tm1 = -1e30f;
        #pragma unroll
        for (int j = 0; j < 8; j++) {
            tm0 = fmaxf(tm0, fmaxf(sa[j][0], sa[j][1]));
            tm1 = fmaxf(tm1, fmaxf(sa[j][2], sa[j][3]));
        }
        tm0 = fmaxf(tm0, __shfl_xor_sync(0xffffffffu, tm0, 1));
        tm0 = fmaxf(tm0, __shfl_xor_sync(0xffffffffu, tm0, 2));
        tm1 = fmaxf(tm1, __shfl_xor_sync(0xffffffffu, tm1, 1));
        tm1 = fmaxf(tm1, __shfl_xor_sync(0xffffffffu, tm1, 2));
        float nm0 = fmaxf(m0, tm0), nm1 = fmaxf(m1, tm1);
        float f0 = __expf(m0 - nm0), f1 = __expf(m1 - nm1);
        float rs0 = 0.f, rs1 = 0.f;
        #pragma unroll
        for (int j = 0; j < 8; j++) {
            sa[j][0] = __expf(sa[j][0] - nm0); rs0 += sa[j][0];
            sa[j][1] = __expf(sa[j][1] - nm0); rs0 += sa[j][1];
            sa[j][2] = __expf(sa[j][2] - nm1); rs1 += sa[j][2];
            sa[j][3] = __expf(sa[j][3] - nm1); rs1 += sa[j][3];
        }
        rs0 += __shfl_xor_sync(0xffffffffu, rs0, 1);
        rs0 += __shfl_xor_sync(0xffffffffu, rs0, 2);
        rs1 += __shfl_xor_sync(0xffffffffu, rs1, 1);
        rs1 += __shfl_xor_sync(0xffffffffu, rs1, 2);
        l0 = l0 * f0 + rs0; l1 = l1 * f1 + rs1;
        m0 = nm0; m1 = nm1;
        #pragma unroll
        for (int dj = 0; dj < 8; dj++) {
            o[dj][0] *= f0; o[dj][1] *= f0; o[dj][2] *= f1; o[dj][3] *= f1;
        }

        // ---- P fragments (in-register split) ----
        uint32_t pah[4][4], pal[4][4];
        #pragma unroll
        for (int kc = 0; kc < 4; kc++) {
            pack_split(sa[2*kc][0],   sa[2*kc][1],   pah[kc][0], pal[kc][0]);
            pack_split(sa[2*kc][2],   sa[2*kc][3],   pah[kc][1], pal[kc][1]);
            pack_split(sa[2*kc+1][0], sa[2*kc+1][1], pah[kc][2], pal[kc][2]);
            pack_split(sa[2*kc+1][2], sa[2*kc+1][3], pah[kc][3], pal[kc][3]);
        }

        // ---- O += P V ----
        #pragma unroll
        for (int kc = 0; kc < 4; kc++) {
            uint32_t bvh[8][2], bvl[8][2];
            #pragma unroll
            for (int dp = 0; dp < 4; dp++) {
                int k = kc * 16 + ((lane >> 3) & 1) * 8 + (lane & 7);
                int d = dp * 16 + (lane >> 4) * 8;
                uint32_t off = SWZ((uint32_t)(k << 7) + (uint32_t)(d << 1));
                uint32_t t0, t1, t2, t3;
                ldsm4t(t0, t1, t2, t3, tb + 16384 + off);
                bvh[2*dp][0]=t0; bvh[2*dp][1]=t1; bvh[2*dp+1][0]=t2; bvh[2*dp+1][1]=t3;
                ldsm4t(t0, t1, t2, t3, tb + 24576 + off);
                bvl[2*dp][0]=t0; bvl[2*dp][1]=t1; bvl[2*dp+1][0]=t2; bvl[2*dp+1][1]=t3;
            }
            #pragma unroll
            for (int dj = 0; dj < 8; dj++) {
                mma16816(o[dj], pah[kc], bvh[dj]);
                mma16816(o[dj], pah[kc], bvl[dj]);
                mma16816(o[dj], pal[kc], bvh[dj]);
            }
        }
    }

    // ---- write y (split bf16) ----
    float il0 = 1.f / l0, il1 = 1.f / l1;
    int row0 = q0 + warp * 16 + r4;
    #pragma unroll
    for (int dj = 0; dj < 8; dj++) {
        int col = h * 64 + dj * 8 + cq;
        bf16 h0, h1, lo0, lo1;
        split2(o[dj][0] * il0, h0, lo0);
        split2(o[dj][1] * il0, h1, lo1);
        *(__nv_bfloat162*)(Yh + (size_t)row0 * D + col) = __halves2bfloat162(h0, h1);
        *(__nv_bfloat162*)(Yl + (size_t)row0 * D + col) = __halves2bfloat162(lo0, lo1);
        split2(o[dj][2] * il1, h0, lo0);
        split2(o[dj][3] * il1, h1, lo1);
        *(__nv_bfloat162*)(Yh + (size_t)(row0 + 8) * D + col) = __halves2bfloat162(h0, h1);
        *(__nv_bfloat162*)(Yl + (size_t)(row0 + 8) * D + col) = __halves2bfloat162(lo0, lo1);
    }
}

// ================= host =================
extern "C" void kernel_launch(void* const* d_in, const int* in_sizes, int n_in,
                              void* d_out, int out_size) {
    const float* x       = (const float*)d_in[0];
    const float* Wq      = (const float*)d_in[1];
    const float* Wk      = (const float*)d_in[2];
    const float* Wv      = (const float*)d_in[3];
    const float* Wo      = (const float*)d_in[4];
    const float* lamb    = (const float*)d_in[5];
    const float* lambdas = (const float*)d_in[6];
    const float* Wfc     = (const float*)d_in[7];
    const float* Wp      = (const float*)d_in[8];
    const int*   levels  = (const int*)d_in[9];
    const int*   sidx    = (const int*)d_in[10];
    float* out = (float*)d_out;

    float *px, *px0, *pxl, *pq, *pk, *pv, *pv1, *pcos, *psin;
    bf16 *pxnh, *pxnl, *pyh, *pyl, *phh, *phl;
    bf16 *pqh, *pql, *pkh, *pkl, *pvh, *pvl;
    bf16 *pwqkvh, *pwqkvl, *pwoh, *pwol, *pwfch, *pwfcl, *pwph, *pwpl;
    unsigned char* pmask; int* pcpad;
    cudaGetSymbolAddress((void**)&px,   g_x);
    cudaGetSymbolAddress((void**)&px0,  g_x0);
    cudaGetSymbolAddress((void**)&pxl,  g_xl);
    cudaGetSymbolAddress((void**)&pq,   g_q);
    cudaGetSymbolAddress((void**)&pk,   g_k);
    cudaGetSymbolAddress((void**)&pv,   g_v);
    cudaGetSymbolAddress((void**)&pv1,  g_v1);
    cudaGetSymbolAddress((void**)&pxnh, g_xnh);
    cudaGetSymbolAddress((void**)&pxnl, g_xnl);
    cudaGetSymbolAddress((void**)&pyh,  g_yh);
    cudaGetSymbolAddress((void**)&pyl,  g_yl);
    cudaGetSymbolAddress((void**)&phh,  g_hh);
    cudaGetSymbolAddress((void**)&phl,  g_hl);
    cudaGetSymbolAddress((void**)&pqh,  g_qh);
    cudaGetSymbolAddress((void**)&pql,  g_ql);
    cudaGetSymbolAddress((void**)&pkh,  g_kh);
    cudaGetSymbolAddress((void**)&pkl,  g_kl);
    cudaGetSymbolAddress((void**)&pvh,  g_vh);
    cudaGetSymbolAddress((void**)&pvl,  g_vl);
    cudaGetSymbolAddress((void**)&pwqkvh, g_wqkvh);
    cudaGetSymbolAddress((void**)&pwqkvl, g_wqkvl);
    cudaGetSymbolAddress((void**)&pwoh,  g_woh);
    cudaGetSymbolAddress((void**)&pwol,  g_wol);
    cudaGetSymbolAddress((void**)&pwfch, g_wfch);
    cudaGetSymbolAddress((void**)&pwfcl, g_wfcl);
    cudaGetSymbolAddress((void**)&pwph,  g_wph);
    cudaGetSymbolAddress((void**)&pwpl,  g_wpl);
    cudaGetSymbolAddress((void**)&pmask, g_mask);
    cudaGetSymbolAddress((void**)&pcpad, g_cpad);
    cudaGetSymbolAddress((void**)&pcos,  g_cos);
    cudaGetSymbolAddress((void**)&psin,  g_sin);

    const int SMEM128 = 3 * (32768 + 2 * 128 * 128);   // 196608
    const int SMEM64  = 3 * (32768 + 2 * 64 * 128);    // 147456
    const int SMEMATT = 16384 + 3 * 36864;             // 126976
    cudaFuncSetAttribute(mma_gemm<128,0>, cudaFuncAttributeMaxDynamicSharedMemorySize, SMEM128);
    cudaFuncSetAttribute(mma_gemm<128,2>, cudaFuncAttributeMaxDynamicSharedMemorySize, SMEM128);
    cudaFuncSetAttribute(mma_gemm<64,1>,  cudaFuncAttributeMaxDynamicSharedMemorySize, SMEM64);
    cudaFuncSetAttribute(attn_mma_kernel, cudaFuncAttributeMaxDynamicSharedMemorySize, SMEMATT);

    const size_t DD = (size_t)D * D, DFD = (size_t)DFF * D;
    split_kernel<<<NL * (int)(DD >> 10), 256>>>(Wq, pwqkvh,          pwqkvl,          20, 3 * DD);
    split_kernel<<<NL * (int)(DD >> 10), 256>>>(Wk, pwqkvh + DD,     pwqkvl + DD,     20, 3 * DD);
    split_kernel<<<NL * (int)(DD >> 10), 256>>>(Wv, pwqkvh + 2 * DD, pwqkvl + 2 * DD, 20, 3 * DD);
    split_kernel<<<NL * (int)(DD >> 10), 256>>>(Wo, pwoh, pwol, 20, DD);
    split_kernel<<<NL * (int)(DFD >> 10), 256>>>(Wfc, pwfch, pwfcl, 22, DFD);
    split_kernel<<<NL * (int)(DFD >> 10), 256>>>(Wp,  pwph,  pwpl,  22, DFD);

    scan_kernel<<<1, S>>>(levels, pcpad);
    mask_kernel<<<(S * S) / 256, 256>>>(levels, sidx, pcpad, pmask);
    ropetab_kernel<<<S, 32>>>(pcos, psin);
    rms_dual_kernel<<<S, 256>>>(x, px, px0);

    for (int i = 0; i < NL; i++) {
        prelayer_kernel<<<S, 256>>>(px, px0, lambdas, i, pxl, pxnh, pxnl);

        mma_gemm<128,0><<<dim3(3 * D / 128, S / 128), 256, SMEM128>>>(
            pxnh, pxnl, pwqkvh + (size_t)i * 3 * DD, pwqkvl + (size_t)i * 3 * DD,
            pq, pk, pv, nullptr, nullptr, nullptr, D, D);

        qkvprep_kernel<<<dim3(S, 4), 128>>>(pq, pk, pv, pv1, lamb, i, pcos, psin,
                                            pqh, pql, pkh, pkl, pvh, pvl);

        attn_mma_kernel<<<dim3(S / 64, H), 128, SMEMATT>>>(
            pqh, pql, pkh, pkl, pvh, pvl, pyh, pyl, pmask);

        mma_gemm<64,1><<<dim3(D / 64, S / 128), 256, SMEM64>>>(
            pyh, pyl, pwoh + (size_t)i * DD, pwol + (size_t)i * DD,
            px, nullptr, nullptr, pxl, nullptr, nullptr, D, D);

        rms_split_kernel<<<S, 256>>>(px, pxnh, pxnl);
        mma_gemm<128,2><<<dim3(DFF / 128, S / 128), 256, SMEM128>>>(
            pxnh, pxnl, pwfch + (size_t)i * DFD, pwfcl + (size_t)i * DFD,
            nullptr, nullptr, nullptr, nullptr, phh, phl, D, DFF);

        mma_gemm<64,1><<<dim3(D / 64, S / 128), 256, SMEM64>>>(
            phh, phl, pwph + (size_t)i * DFD, pwpl + (size_t)i * DFD,
            px, nullptr, nullptr, px, nullptr, nullptr, DFF, D);
    }

    rms_dual_kernel<<<S, 256>>>(px, out, nullptr);
}

// round 13
// speedup vs baseline: 1.1057x; 1.1057x over previous
#include <cuda_runtime.h>
#include <cuda_bf16.h>
#include <math.h>
#include <stdint.h>

#define S 1024
#define D 1024
#define H 16
#define HD 64
#define NL 6
#define DFF 4096
#define EPS 1.1920929e-07f

typedef __nv_bfloat16 bf16;

// ================= device scratch (no allocations allowed) =================
__device__ float g_x [S*D];
__device__ float g_x0[S*D];
__device__ float g_xl[S*D];
__device__ float g_q [S*D];
__device__ float g_k [S*D];
__device__ float g_v [S*D];
__device__ float g_v1[S*D];
__device__ bf16  g_xnh[S*D],  g_xnl[S*D];
__device__ bf16  g_yh [S*D],  g_yl [S*D];
__device__ bf16  g_hh [S*DFF], g_hl [S*DFF];
__device__ bf16  g_qh[S*D], g_ql[S*D];
__device__ bf16  g_kh[S*D], g_kl[S*D];
__device__ bf16  g_vh[S*D], g_vl[S*D];
__device__ bf16  g_wqkvh[(size_t)NL*3*D*D], g_wqkvl[(size_t)NL*3*D*D];
__device__ bf16  g_woh  [(size_t)NL*D*D],   g_wol  [(size_t)NL*D*D];
__device__ bf16  g_wfch [(size_t)NL*DFF*D], g_wfcl [(size_t)NL*DFF*D];
__device__ bf16  g_wph  [(size_t)NL*D*DFF], g_wpl  [(size_t)NL*D*DFF];
__device__ unsigned char g_mask[S*S];
__device__ int   g_cpad[S+1];
__device__ float g_cos[S*32];
__device__ float g_sin[S*32];

// ================= helpers =================
#define SWZ(x) ((x) ^ (((x) >> 3) & 0x70))

__device__ __forceinline__ uint32_t smem_u32(const void* p) {
    return (uint32_t)__cvta_generic_to_shared((void*)p);
}
#define CP16(dst, src) asm volatile("cp.async.cg.shared.global [%0], [%1], 16;" :: "r"(dst), "l"(src) : "memory")
#define CP_COMMIT()    asm volatile("cp.async.commit_group;" ::: "memory")
#define CP_WAIT(n)     asm volatile("cp.async.wait_group %0;" :: "n"(n) : "memory")

__device__ __forceinline__ void ldsm4(uint32_t& a0, uint32_t& a1, uint32_t& a2, uint32_t& a3,
                                      uint32_t addr) {
    asm volatile("ldmatrix.sync.aligned.m8n8.x4.shared.b16 {%0,%1,%2,%3}, [%4];"
                 : "=r"(a0), "=r"(a1), "=r"(a2), "=r"(a3) : "r"(addr));
}
__device__ __forceinline__ void ldsm4t(uint32_t& a0, uint32_t& a1, uint32_t& a2, uint32_t& a3,
                                       uint32_t addr) {
    asm volatile("ldmatrix.sync.aligned.m8n8.x4.trans.shared.b16 {%0,%1,%2,%3}, [%4];"
                 : "=r"(a0), "=r"(a1), "=r"(a2), "=r"(a3) : "r"(addr));
}
__device__ __forceinline__ void mma16816(float* c, const uint32_t* a, const uint32_t* b) {
    asm volatile("mma.sync.aligned.m16n8k16.row.col.f32.bf16.bf16.f32 "
                 "{%0,%1,%2,%3}, {%4,%5,%6,%7}, {%8,%9}, {%0,%1,%2,%3};"
                 : "+f"(c[0]), "+f"(c[1]), "+f"(c[2]), "+f"(c[3])
                 : "r"(a[0]), "r"(a[1]), "r"(a[2]), "r"(a[3]), "r"(b[0]), "r"(b[1]));
}
__device__ __forceinline__ void split2(float v, bf16& h, bf16& l) {
    h = __float2bfloat16(v);
    l = __float2bfloat16(v - __bfloat162float(h));
}
__device__ __forceinline__ uint32_t pack2(bf16 a, bf16 b) {
    __nv_bfloat162 v2 = __halves2bfloat162(a, b);
    return *reinterpret_cast<uint32_t*>(&v2);
}
__device__ __forceinline__ void pack_split(float a, float b, uint32_t& ph, uint32_t& pl) {
    bf16 ah, al, bh_, bl_;
    split2(a, ah, al); split2(b, bh_, bl_);
    ph = pack2(ah, bh_);
    pl = pack2(al, bl_);
}

// ================= setup kernels =================
__global__ void scan_kernel(const int* __restrict__ levels, int* __restrict__ cpad) {
    __shared__ int sh[S];
    int t = threadIdx.x;
    sh[t] = (levels[t] == 0) ? 1 : 0;
    __syncthreads();
    for (int off = 1; off < S; off <<= 1) {
        int add = (t >= off) ? sh[t - off] : 0;
        __syncthreads();
        sh[t] += add;
        __syncthreads();
    }
    cpad[t + 1] = sh[t];
    if (t == 0) cpad[0] = 0;
}

__global__ void mask_kernel(const int* __restrict__ levels, const int* __restrict__ sidx,
                            const int* __restrict__ cpad, unsigned char* __restrict__ mk) {
    int idx = blockIdx.x * 256 + threadIdx.x;
    int i = idx >> 10, j = idx & 1023;
    bool causal = (i >= j);
    bool same   = (sidx[i] == sidx[j]);
    int  cnt    = cpad[i] - cpad[j + 1];
    bool markov = (levels[j] == 0) && (cnt > 0);
    mk[idx] = (causal && same && !markov) ? 1 : 0;
}

__global__ void ropetab_kernel(float* __restrict__ ct, float* __restrict__ st) {
    int t = blockIdx.x, l = threadIdx.x;
    double inv = pow(10000.0, -(double)(2 * l) / (double)HD);
    double fr  = (double)t * inv;
    ct[t * 32 + l] = (float)cos(fr);
    st[t * 32 + l] = (float)sin(fr);
}

// split fp32 -> (hi,lo) bf16. 8 elements/thread, 16B coalesced stores.
__global__ __launch_bounds__(256) void split_kernel(const float* __restrict__ src,
                                                    bf16* __restrict__ h, bf16* __restrict__ l,
                                                    int lg2, size_t dstStride) {
    size_t idx = (size_t)blockIdx.x * 256 + threadIdx.x;
    size_t e = idx << 3;
    int layer = (int)(e >> lg2);
    size_t off = e & (((size_t)1 << lg2) - 1);
    size_t dpos = (size_t)layer * dstStride + off;
    float4 v0 = *(const float4*)(src + e);
    float4 v1 = *(const float4*)(src + e + 4);
    bf16 h0,h1,h2,h3,h4,h5,h6,h7, l0,l1,l2,l3,l4,l5,l6,l7;
    split2(v0.x,h0,l0); split2(v0.y,h1,l1); split2(v0.z,h2,l2); split2(v0.w,h3,l3);
    split2(v1.x,h4,l4); split2(v1.y,h5,l5); split2(v1.z,h6,l6); split2(v1.w,h7,l7);
    uint4 hv, lv;
    hv.x = pack2(h0,h1); hv.y = pack2(h2,h3); hv.z = pack2(h4,h5); hv.w = pack2(h6,h7);
    lv.x = pack2(l0,l1); lv.y = pack2(l2,l3); lv.z = pack2(l4,l5); lv.w = pack2(l6,l7);
    *(uint4*)(h + dpos) = hv;
    *(uint4*)(l + dpos) = lv;
}

// ================= rms / prelayer (float4, register-resident) =================
__device__ __forceinline__ float blk_reduce(float s, float* red, int tid) {
    #pragma unroll
    for (int o = 16; o; o >>= 1) s += __shfl_xor_sync(0xffffffffu, s, o);
    if ((tid & 31) == 0) red[tid >> 5] = s;
    __syncthreads();
    if (tid == 0) {
        float t2 = 0.f;
        #pragma unroll
        for (int w = 0; w < 8; w++) t2 += red[w];
        red[0] = t2;
    }
    __syncthreads();
    return red[0];
}

__global__ __launch_bounds__(256) void rms_dual_kernel(const float* __restrict__ in,
                                                       float* __restrict__ out1,
                                                       float* __restrict__ out2) {
    __shared__ float red[8];
    int row = blockIdx.x, tid = threadIdx.x;
    float4 v = ((const float4*)(in + (size_t)row * D))[tid];
    float ss = blk_reduce(v.x*v.x + v.y*v.y + v.z*v.z + v.w*v.w, red, tid);
    float sc = rsqrtf(ss * (1.0f / D) + EPS);
    v.x *= sc; v.y *= sc; v.z *= sc; v.w *= sc;
    ((float4*)(out1 + (size_t)row * D))[tid] = v;
    if (out2) ((float4*)(out2 + (size_t)row * D))[tid] = v;
}

__global__ __launch_bounds__(256) void rms_split_kernel(const float* __restrict__ in,
                                                        bf16* __restrict__ oh, bf16* __restrict__ ol) {
    __shared__ float red[8];
    int row = blockIdx.x, tid = threadIdx.x;
    float4 v = ((const float4*)(in + (size_t)row * D))[tid];
    float ss = blk_reduce(v.x*v.x + v.y*v.y + v.z*v.z + v.w*v.w, red, tid);
    float sc = rsqrtf(ss * (1.0f / D) + EPS);
    bf16 h0,h1,h2,h3,l0,l1,l2,l3;
    split2(v.x*sc,h0,l0); split2(v.y*sc,h1,l1); split2(v.z*sc,h2,l2); split2(v.w*sc,h3,l3);
    size_t p = (size_t)row * D + tid * 4;
    *(__nv_bfloat162*)(oh+p)   = __halves2bfloat162(h0,h1);
    *(__nv_bfloat162*)(oh+p+2) = __halves2bfloat162(h2,h3);
    *(__nv_bfloat162*)(ol+p)   = __halves2bfloat162(l0,l1);
    *(__nv_bfloat162*)(ol+p+2) = __halves2bfloat162(l2,l3);
}

__global__ __launch_bounds__(256) void prelayer_kernel(const float* __restrict__ x,
                                                       const float* __restrict__ x0,
                                                       const float* __restrict__ lambdas, int layer,
                                                       float* __restrict__ xl,
                                                       bf16* __restrict__ oh, bf16* __restrict__ ol) {
    __shared__ float red[8];
    int row = blockIdx.x, tid = threadIdx.x;
    float la = lambdas[2 * layer], lb = lambdas[2 * layer + 1];
    float4 a = ((const float4*)(x  + (size_t)row * D))[tid];
    float4 b = ((const float4*)(x0 + (size_t)row * D))[tid];
    float4 v = make_float4(la*a.x + lb*b.x, la*a.y + lb*b.y, la*a.z + lb*b.z, la*a.w + lb*b.w);
    ((float4*)(xl + (size_t)row * D))[tid] = v;
    float ss = blk_reduce(v.x*v.x + v.y*v.y + v.z*v.z + v.w*v.w, red, tid);
    float sc = rsqrtf(ss * (1.0f / D) + EPS);
    bf16 h0,h1,h2,h3,l0,l1,l2,l3;
    split2(v.x*sc,h0,l0); split2(v.y*sc,h1,l1); split2(v.z*sc,h2,l2); split2(v.w*sc,h3,l3);
    size_t p = (size_t)row * D + tid * 4;
    *(__nv_bfloat162*)(oh+p)   = __halves2bfloat162(h0,h1);
    *(__nv_bfloat162*)(oh+p+2) = __halves2bfloat162(h2,h3);
    *(__nv_bfloat162*)(ol+p)   = __halves2bfloat162(l0,l1);
    *(__nv_bfloat162*)(ol+p+2) = __halves2bfloat162(l2,l3);
}

// ================= mma.sync split-bf16 GEMM: BM x BN tiles, 2 CTA/SM =================
// C[BM x BN tile] = (Ah+Al)[M,K] @ (Bh+Bl)[N,K]^T   (3-term split)
// EPI 0: QKV fp32 de-concat (ld 1024); EPI 1: C0 = Res + acc; EPI 2: split(relu(acc)^2)
template <int BM, int BN, int EPI>
__global__ __launch_bounds__(256, 2) void mma_gemm(
    const bf16* __restrict__ Ah, const bf16* __restrict__ Al,
    const bf16* __restrict__ Bh, const bf16* __restrict__ Bl,
    float* __restrict__ C0, float* __restrict__ C1, float* __restrict__ C2,
    const float* __restrict__ Res, bf16* __restrict__ Hh, bf16* __restrict__ Hl,
    int K, int ldC)
{
    constexpr int WM = (BN == 128) ? 2 : 4;    // warp grid rows
    constexpr int WN = 8 / WM;                 // warp grid cols
    constexpr int MI = BM / (WM * 16);         // m16 tiles per warp
    constexpr int NJ = BN / (WN * 8);          // n8 tiles per warp
    constexpr int RW = BM / WM;                // rows per warp
    constexpr int CW = BN / WN;                // cols per warp
    constexpr int ASTRIDE = BM * 128;          // bytes per A term
    constexpr int BSTRIDE = BN * 128;          // bytes per B term
    constexpr int STAGE = 2 * ASTRIDE + 2 * BSTRIDE;
    extern __shared__ char smem[];
    const uint32_t sb = smem_u32(smem);
    const int tid  = threadIdx.x;
    const int warp = tid >> 5, lane = tid & 31;
    const int wm = warp % WM, wn = warp / WM;
    const int row0 = blockIdx.y * BM, col0 = blockIdx.x * BN;

    auto load_chunk = [&](int st, int c) {
        uint32_t tb = sb + st * STAGE;
        int k0 = c << 6;
        #pragma unroll
        for (int i = tid; i < BM * 8; i += 256) {
            int r = i >> 3, e = (i & 7) << 3;
            uint32_t so = SWZ((uint32_t)(r << 7) + (e << 1));
            size_t ga = (size_t)(row0 + r) * K + k0 + e;
            CP16(tb + so,           Ah + ga);
            CP16(tb + ASTRIDE + so, Al + ga);
        }
        #pragma unroll
        for (int i = tid; i < BN * 8; i += 256) {
            int r = i >> 3, e = (i & 7) << 3;
            uint32_t so = SWZ((uint32_t)(r << 7) + (e << 1));
            size_t gb = (size_t)(col0 + r) * K + k0 + e;
            CP16(tb + 2 * ASTRIDE + so,            Bh + gb);
            CP16(tb + 2 * ASTRIDE + BSTRIDE + so,  Bl + gb);
        }
        CP_COMMIT();
    };

    float acc[MI][NJ][4];
    #pragma unroll
    for (int i = 0; i < MI; i++)
        #pragma unroll
        for (int j = 0; j < NJ; j++)
            #pragma unroll
            for (int r = 0; r < 4; r++) acc[i][j][r] = 0.f;

    load_chunk(0, 0);
    load_chunk(1, 1);

    const int NC = K >> 6;
    const int lrow = lane & 15;
    const uint32_t lk = (uint32_t)(lane >> 4) << 4;

    for (int c = 0; c < NC; c++) {
        const int st = c & 1;
        if (c + 1 < NC) { CP_WAIT(1); } else { CP_WAIT(0); }
        __syncthreads();
        const uint32_t aB = sb + st * STAGE;
        const uint32_t bB = aB + 2 * ASTRIDE;
        #pragma unroll
        for (int ks = 0; ks < 4; ks++) {
            uint32_t ah[MI][4], al[MI][4], bh[NJ][2], bl[NJ][2];
            #pragma unroll
            for (int i = 0; i < MI; i++) {
                int r = wm * RW + i * 16 + lrow;
                uint32_t off = SWZ((uint32_t)(r << 7) + (uint32_t)(ks << 5) + lk);
                ldsm4(ah[i][0], ah[i][1], ah[i][2], ah[i][3], aB + off);
                ldsm4(al[i][0], al[i][1], al[i][2], al[i][3], aB + ASTRIDE + off);
            }
            #pragma unroll
            for (int jp = 0; jp < NJ / 2; jp++) {
                int r = wn * CW + jp * 16 + lrow;
                uint32_t off = SWZ((uint32_t)(r << 7) + (uint32_t)(ks << 5) + lk);
                uint32_t t0, t1, t2, t3;
                ldsm4(t0, t1, t2, t3, bB + off);
                bh[2*jp][0] = t0; bh[2*jp][1] = t2;
                bh[2*jp+1][0] = t1; bh[2*jp+1][1] = t3;
                ldsm4(t0, t1, t2, t3, bB + BSTRIDE + off);
                bl[2*jp][0] = t0; bl[2*jp][1] = t2;
                bl[2*jp+1][0] = t1; bl[2*jp+1][1] = t3;
            }
            #pragma unroll
            for (int i = 0; i < MI; i++)
                #pragma unroll
                for (int j = 0; j < NJ; j++) {
                    mma16816(acc[i][j], ah[i], bh[j]);
                    mma16816(acc[i][j], ah[i], bl[j]);
                    mma16816(acc[i][j], al[i], bh[j]);
                }
        }
        __syncthreads();
        if (c + 2 < NC) load_chunk(st, c + 2);
    }

    const int rbase = row0 + wm * RW + (lane >> 2);
    const int cwarp = wn * CW + (lane & 3) * 2;

    if (EPI == 0) {
        float* C = C0; int cg0 = col0;
        if (col0 >= 2048)      { C = C2; cg0 = col0 - 2048; }
        else if (col0 >= 1024) { C = C1; cg0 = col0 - 1024; }
        #pragma unroll
        for (int i = 0; i < MI; i++)
            #pragma unroll
            for (int j = 0; j < NJ; j++) {
                int cc = cg0 + cwarp + j * 8;
                *(float2*)(C + (size_t)(rbase + i * 16)     * 1024 + cc) = make_float2(acc[i][j][0], acc[i][j][1]);
                *(float2*)(C + (size_t)(rbase + i * 16 + 8) * 1024 + cc) = make_float2(acc[i][j][2], acc[i][j][3]);
            }
    } else if (EPI == 1) {
        #pragma unroll
        for (int i = 0; i < MI; i++)
            #pragma unroll
            for (int j = 0; j < NJ; j++) {
                int cc = col0 + cwarp + j * 8;
                #pragma unroll
                for (int hh2 = 0; hh2 < 2; hh2++) {
                    size_t off = (size_t)(rbase + i * 16 + hh2 * 8) * ldC + cc;
                    float2 rv = *(const float2*)(Res + off);
                    *(float2*)(C0 + off) = make_float2(acc[i][j][2*hh2] + rv.x,
                                                       acc[i][j][2*hh2+1] + rv.y);
                }
            }
    } else {
        #pragma unroll
        for (int i = 0; i < MI; i++)
            #pragma unroll
            for (int j = 0; j < NJ; j++) {
                int cc = col0 + cwarp + j * 8;
                #pragma unroll
                for (int hh2 = 0; hh2 < 2; hh2++) {
                    size_t off = (size_t)(rbase + i * 16 + hh2 * 8) * ldC + cc;
                    float p0 = fmaxf(acc[i][j][2*hh2],   0.f); p0 *= p0;
                    float p1 = fmaxf(acc[i][j][2*hh2+1], 0.f); p1 *= p1;
                    bf16 h0, h1, l0, l1;
                    split2(p0, h0, l0); split2(p1, h1, l1);
                    *(__nv_bfloat162*)(Hh + off) = __halves2bfloat162(h0, h1);
                    *(__nv_bfloat162*)(Hl + off) = __halves2bfloat162(l0, l1);
                }
            }
    }
}

// ================= qkvprep: per-head rms + rope + vmix -> split bf16 =================
__global__ __launch_bounds__(128) void qkvprep_kernel(
    const float* __restrict__ Q, const float* __restrict__ Kt, const float* __restrict__ V,
    float* __restrict__ V1, const float* __restrict__ lamb, int layer,
    const float* __restrict__ ctab, const float* __restrict__ stab,
    bf16* __restrict__ qh, bf16* __restrict__ ql,
    bf16* __restrict__ kh, bf16* __restrict__ kl,
    bf16* __restrict__ vh, bf16* __restrict__ vl)
{
    int t = blockIdx.x;
    int h = blockIdx.y * 4 + (threadIdx.x >> 5);
    int lane = threadIdx.x & 31;
    int base = t * D + h * HD;
    float c  = ctab[t * 32 + lane];
    float sn = stab[t * 32 + lane];
    bf16 hh, ll;

    float a = Q[base + lane], b = Q[base + 32 + lane];
    float s = a * a + b * b;
    #pragma unroll
    for (int o = 16; o; o >>= 1) s += __shfl_xor_sync(0xffffffffu, s, o);
    float r = rsqrtf(s * (1.0f / HD) + EPS);
    a *= r; b *= r;
    float ra = ( a * c + b * sn) * 0.125f;
    float rb = (-a * sn + b * c) * 0.125f;
    split2(ra, hh, ll); qh[base + lane] = hh;      ql[base + lane] = ll;
    split2(rb, hh, ll); qh[base + 32 + lane] = hh; ql[base + 32 + lane] = ll;

    a = Kt[base + lane]; b = Kt[base + 32 + lane];
    s = a * a + b * b;
    #pragma unroll
    for (int o = 16; o; o >>= 1) s += __shfl_xor_sync(0xffffffffu, s, o);
    r = rsqrtf(s * (1.0f / HD) + EPS);
    a *= r; b *= r;
    ra =  a * c + b * sn;
    rb = -a * sn + b * c;
    split2(ra, hh, ll); kh[base + lane] = hh;      kl[base + lane] = ll;
    split2(rb, hh, ll); kh[base + 32 + lane] = hh; kl[base + 32 + lane] = ll;

    float lm = lamb[layer];
    float v0 = V[base + lane], v1 = V[base + 32 + lane];
    if (layer == 0) { V1[base + lane] = v0; V1[base + 32 + lane] = v1; }
    float w0 = V1[base + lane], w1 = V1[base + 32 + lane];
    v0 = (1.f - lm) * v0 + lm * w0;
    v1 = (1.f - lm) * v1 + lm * w1;
    split2(v0, hh, ll); vh[base + lane] = hh;      vl[base + lane] = ll;
    split2(v1, hh, ll); vh[base + 32 + lane] = hh; vl[base + 32 + lane] = ll;
}

// ================= tensor-core flash attention (split bf16, 2-stage, 2 CTA/SM) =================
__global__ __launch_bounds__(128) void attn_mma_kernel(
    const bf16* __restrict__ Qh, const bf16* __restrict__ Ql,
    const bf16* __restrict__ Kh, const bf16* __restrict__ Kl,
    const bf16* __restrict__ Vh, const bf16* __restrict__ Vl,
    bf16* __restrict__ Yh, bf16* __restrict__ Yl,
    const unsigned char* __restrict__ mk)
{
    extern __shared__ __align__(128) char sm[];
    const int h  = blockIdx.y;
    const int qb = gridDim.x - 1 - blockIdx.x;   // heavy blocks first
    const int q0 = qb * 64;
    const int tid = threadIdx.x, warp = tid >> 5, lane = tid & 31;
    const uint32_t sb = smem_u32(sm);
    const int NT = qb + 1;

    for (int i = tid; i < 512; i += 128) {
        int r = i >> 3, e = (i & 7) << 3;
        uint32_t so = SWZ((uint32_t)(r << 7) + (e << 1));
        size_t g = (size_t)(q0 + r) * D + h * 64 + e;
        CP16(sb + so,        Qh + g);
        CP16(sb + 8192 + so, Ql + g);
    }
    CP_COMMIT();

    auto load_stage = [&](int st, int kt) {
        uint32_t tb = sb + 16384 + st * 36864;
        int k0 = kt * 64;
        for (int i = tid; i < 512; i += 128) {
            int r = i >> 3, e = (i & 7) << 3;
            uint32_t so = SWZ((uint32_t)(r << 7) + (e << 1));
            size_t g = (size_t)(k0 + r) * D + h * 64 + e;
            CP16(tb + so,         Kh + g);
            CP16(tb + 8192 + so,  Kl + g);
            CP16(tb + 16384 + so, Vh + g);
            CP16(tb + 24576 + so, Vl + g);
        }
        for (int i = tid; i < 256; i += 128) {
            int r = i >> 2, e = (i & 3) << 4;
            CP16(tb + 32768 + (r << 6) + e, mk + (size_t)(q0 + r) * S + k0 + e);
        }
        CP_COMMIT();
    };
    load_stage(0, 0);
    if (NT > 1) load_stage(1, 1);

    float m0 = -1e30f, m1 = -1e30f, l0 = 0.f, l1 = 0.f;
    float o[8][4] = {};
    const int r4 = lane >> 2;
    const int cq = (lane & 3) << 1;
    const int lrow = lane & 15;
    const uint32_t lkb = (uint32_t)(lane >> 4) << 4;

    for (int kt = 0; kt < NT; kt++) {
        const int st = kt & 1;
        if (kt + 1 < NT) { CP_WAIT(1); } else { CP_WAIT(0); }
        __syncthreads();
        const uint32_t tb = sb + 16384 + st * 36864;
        const char* mbase = sm + 16384 + st * 36864 + 32768;

        // ---- S = Q K^T ----
        float sa[8][4] = {};
        #pragma unroll
        for (int ks = 0; ks < 4; ks++) {
            uint32_t qah[4], qal[4];
            {
                uint32_t off = SWZ((uint32_t)((warp * 16 + lrow) << 7) + (uint32_t)(ks << 5) + lkb);
                ldsm4(qah[0], qah[1], qah[2], qah[3], sb + off);
                ldsm4(qal[0], qal[1], qal[2], qal[3], sb + 8192 + off);
            }
            uint32_t bh[8][2], bl[8][2];
            #pragma unroll
            for (int jp = 0; jp < 4; jp++) {
                uint32_t off = SWZ((uint32_t)((jp * 16 + lrow) << 7) + (uint32_t)(ks << 5) + lkb);
                uint32_t t0, t1, t2, t3;
                ldsm4(t0, t1, t2, t3, tb + off);
                bh[2*jp][0]=t0; bh[2*jp][1]=t2; bh[2*jp+1][0]=t1; bh[2*jp+1][1]=t3;
                ldsm4(t0, t1, t2, t3, tb + 8192 + off);
                bl[2*jp][0]=t0; bl[2*jp][1]=t2; bl[2*jp+1][0]=t1; bl[2*jp+1][1]=t3;
            }
            #pragma unroll
            for (int j = 0; j < 8; j++) {
                mma16816(sa[j], qah, bh[j]);
                mma16816(sa[j], qah, bl[j]);
                mma16816(sa[j], qal, bh[j]);
            }
        }

        // ---- mask ----
        #pragma unroll
        for (int j = 0; j < 8; j++) {
            int c0 = j * 8 + cq;
            unsigned short mw0 = *(const unsigned short*)(mbase + ((warp*16 + r4)     << 6) + c0);
            unsigned short mw1 = *(const unsigned short*)(mbase + ((warp*16 + r4 + 8) << 6) + c0);
            sa[j][0] = (mw0 & 0xff) ? sa[j][0] : -1e30f;
            sa[j][1] = (mw0 >> 8)   ? sa[j][1] : -1e30f;
            sa[j][2] = (mw1 & 0xff) ? sa[j][2] : -1e30f;
            sa[j][3] = (mw1 >> 8)   ? sa[j][3] : -1e30f;
        }

        // ---- online softmax ----
        float tm0 = -1e30f, tm1 = -1e30f;
        #pragma unroll
        for (int j = 0; j < 8; j++) {
            tm0 = fmaxf(tm0, fmaxf(sa[j][0], sa[j][1]));
            tm1 = fmaxf(tm1, fmaxf(sa[j][2], sa[j][3]));
        }
        tm0 = fmaxf(tm0, __shfl_xor_sync(0xffffffffu, tm0, 1));
        tm0 = fmaxf(tm0, __shfl_xor_sync(0xffffffffu, tm0, 2));
        tm1 = fmaxf(tm1, __shfl_xor_sync(0xffffffffu, tm1, 1));
        tm1 = fmaxf(tm1, __shfl_xor_sync(0xffffffffu, tm1, 2));
        float nm0 = fmaxf(m0, tm0), nm1 = fmaxf(m1, tm1);
        float f0 = __expf(m0 - nm0), f1 = __expf(m1 - nm1);
        float rs0 = 0.f, rs1 = 0.f;
        #pragma unroll
        for (int j = 0; j < 8; j++) {
            sa[j][0] = __expf(sa[j][0] - nm0); rs0 += sa[j][0];
            sa[j][1] = __expf(sa[j][1] - nm0); rs0 += sa[j][1];
            sa[j][2] = __expf(sa[j][2] - nm1); rs1 += sa[j][2];
            sa[j][3] = __expf(sa[j][3] - nm1); rs1 += sa[j][3];
        }
        rs0 += __shfl_xor_sync(0xffffffffu, rs0, 1);
        rs0 += __shfl_xor_sync(0xffffffffu, rs0, 2);
        rs1 += __shfl_xor_sync(0xffffffffu, rs1, 1);
        rs1 += __shfl_xor_sync(0xffffffffu, rs1, 2);
        l0 = l0 * f0 + rs0; l1 = l1 * f1 + rs1;
        m0 = nm0; m1 = nm1;
        #pragma unroll
        for (int dj = 0; dj < 8; dj++) {
            o[dj][0] *= f0; o[dj][1] *= f0; o[dj][2] *= f1; o[dj][3] *= f1;
        }

        // ---- P fragments (in-register split) ----
        uint32_t pah[4][4], pal[4][4];
        #pragma unroll
        for (int kc = 0; kc < 4; kc++) {
            pack_split(sa[2*kc][0],   sa[2*kc][1],   pah[kc][0], pal[kc][0]);
            pack_split(sa[2*kc][2],   sa[2*kc][3],   pah[kc][1], pal[kc][1]);
            pack_split(sa[2*kc+1][0], sa[2*kc+1][1], pah[kc][2], pal[kc][2]);
            pack_split(sa[2*kc+1][2], sa[2*kc+1][3], pah[kc][3], pal[kc][3]);
        }

        // ---- O += P V ----
        #pragma unroll
        for (int kc = 0; kc < 4; kc++) {
            uint32_t bvh[8][2], bvl[8][2];
            #pragma unroll
            for (int dp = 0; dp < 4; dp++) {
                int k = kc * 16 + ((lane >> 3) & 1) * 8 + (lane & 7);
                int d = dp * 16 + (lane >> 4) * 8;
                uint32_t off = SWZ((uint32_t)(k << 7) + (uint32_t)(d << 1));
                uint32_t t0, t1, t2, t3;
                ldsm4t(t0, t1, t2, t3, tb + 16384 + off);
                bvh[2*dp][0]=t0; bvh[2*dp][1]=t1; bvh[2*dp+1][0]=t2; bvh[2*dp+1][1]=t3;
                ldsm4t(t0, t1, t2, t3, tb + 24576 + off);
                bvl[2*dp][0]=t0; bvl[2*dp][1]=t1; bvl[2*dp+1][0]=t2; bvl[2*dp+1][1]=t3;
            }
            #pragma unroll
            for (int dj = 0; dj < 8; dj++) {
                mma16816(o[dj], pah[kc], bvh[dj]);
                mma16816(o[dj], pah[kc], bvl[dj]);
                mma16816(o[dj], pal[kc], bvh[dj]);
            }
        }
        __syncthreads();
        if (kt + 2 < NT) load_stage(st, kt + 2);
    }

    // ---- write y (split bf16) ----
    float il0 = 1.f / l0, il1 = 1.f / l1;
    int row0 = q0 + warp * 16 + r4;
    #pragma unroll
    for (int dj = 0; dj < 8; dj++) {
        int col = h * 64 + dj * 8 + cq;
        bf16 h0, h1, lo0, lo1;
        split2(o[dj][0] * il0, h0, lo0);
        split2(o[dj][1] * il0, h1, lo1);
        *(__nv_bfloat162*)(Yh + (size_t)row0 * D + col) = __halves2bfloat162(h0, h1);
        *(__nv_bfloat162*)(Yl + (size_t)row0 * D + col) = __halves2bfloat162(lo0, lo1);
        split2(o[dj][2] * il1, h0, lo0);
        split2(o[dj][3] * il1, h1, lo1);
        *(__nv_bfloat162*)(Yh + (size_t)(row0 + 8) * D + col) = __halves2bfloat162(h0, h1);
        *(__nv_bfloat162*)(Yl + (size_t)(row0 + 8) * D + col) = __halves2bfloat162(lo0, lo1);
    }
}

// ================= host =================
extern "C" void kernel_launch(void* const* d_in, const int* in_sizes, int n_in,
                              void* d_out, int out_size) {
    const float* x       = (const float*)d_in[0];
    const float* Wq      = (const float*)d_in[1];
    const float* Wk      = (const float*)d_in[2];
    const float* Wv      = (const float*)d_in[3];
    const float* Wo      = (const float*)d_in[4];
    const float* lamb    = (const float*)d_in[5];
    const float* lambdas = (const float*)d_in[6];
    const float* Wfc     = (const float*)d_in[7];
    const float* Wp      = (const float*)d_in[8];
    const int*   levels  = (const int*)d_in[9];
    const int*   sidx    = (const int*)d_in[10];
    float* out = (float*)d_out;

    float *px, *px0, *pxl, *pq, *pk, *pv, *pv1, *pcos, *psin;
    bf16 *pxnh, *pxnl, *pyh, *pyl, *phh, *phl;
    bf16 *pqh, *pql, *pkh, *pkl, *pvh, *pvl;
    bf16 *pwqkvh, *pwqkvl, *pwoh, *pwol, *pwfch, *pwfcl, *pwph, *pwpl;
    unsigned char* pmask; int* pcpad;
    cudaGetSymbolAddress((void**)&px,   g_x);
    cudaGetSymbolAddress((void**)&px0,  g_x0);
    cudaGetSymbolAddress((void**)&pxl,  g_xl);
    cudaGetSymbolAddress((void**)&pq,   g_q);
    cudaGetSymbolAddress((void**)&pk,   g_k);
    cudaGetSymbolAddress((void**)&pv,   g_v);
    cudaGetSymbolAddress((void**)&pv1,  g_v1);
    cudaGetSymbolAddress((void**)&pxnh, g_xnh);
    cudaGetSymbolAddress((void**)&pxnl, g_xnl);
    cudaGetSymbolAddress((void**)&pyh,  g_yh);
    cudaGetSymbolAddress((void**)&pyl,  g_yl);
    cudaGetSymbolAddress((void**)&phh,  g_hh);
    cudaGetSymbolAddress((void**)&phl,  g_hl);
    cudaGetSymbolAddress((void**)&pqh,  g_qh);
    cudaGetSymbolAddress((void**)&pql,  g_ql);
    cudaGetSymbolAddress((void**)&pkh,  g_kh);
    cudaGetSymbolAddress((void**)&pkl,  g_kl);
    cudaGetSymbolAddress((void**)&pvh,  g_vh);
    cudaGetSymbolAddress((void**)&pvl,  g_vl);
    cudaGetSymbolAddress((void**)&pwqkvh, g_wqkvh);
    cudaGetSymbolAddress((void**)&pwqkvl, g_wqkvl);
    cudaGetSymbolAddress((void**)&pwoh,  g_woh);
    cudaGetSymbolAddress((void**)&pwol,  g_wol);
    cudaGetSymbolAddress((void**)&pwfch, g_wfch);
    cudaGetSymbolAddress((void**)&pwfcl, g_wfcl);
    cudaGetSymbolAddress((void**)&pwph,  g_wph);
    cudaGetSymbolAddress((void**)&pwpl,  g_wpl);
    cudaGetSymbolAddress((void**)&pmask, g_mask);
    cudaGetSymbolAddress((void**)&pcpad, g_cpad);
    cudaGetSymbolAddress((void**)&pcos,  g_cos);
    cudaGetSymbolAddress((void**)&psin,  g_sin);

    // 2-stage smem: stage = 2*BM*128 + 2*BN*128
    const int SMEM_6412 = 2 * (2 * 64 * 128 + 2 * 128 * 128);  // 98304
    const int SMEM_6464 = 2 * (2 * 64 * 128 + 2 * 64 * 128);   // 65536
    const int SMEMATT   = 16384 + 2 * 36864;                   // 90112
    cudaFuncSetAttribute(mma_gemm<64,128,0>, cudaFuncAttributeMaxDynamicSharedMemorySize, SMEM_6412);
    cudaFuncSetAttribute(mma_gemm<64,128,2>, cudaFuncAttributeMaxDynamicSharedMemorySize, SMEM_6412);
    cudaFuncSetAttribute(mma_gemm<64,64,1>,  cudaFuncAttributeMaxDynamicSharedMemorySize, SMEM_6464);
    cudaFuncSetAttribute(attn_mma_kernel,    cudaFuncAttributeMaxDynamicSharedMemorySize, SMEMATT);

    const size_t DD = (size_t)D * D, DFD = (size_t)DFF * D;
    split_kernel<<<NL * (int)(DD >> 11), 256>>>(Wq, pwqkvh,          pwqkvl,          20, 3 * DD);
    split_kernel<<<NL * (int)(DD >> 11), 256>>>(Wk, pwqkvh + DD,     pwqkvl + DD,     20, 3 * DD);
    split_kernel<<<NL * (int)(DD >> 11), 256>>>(Wv, pwqkvh + 2 * DD, pwqkvl + 2 * DD, 20, 3 * DD);
    split_kernel<<<NL * (int)(DD >> 11), 256>>>(Wo, pwoh, pwol, 20, DD);
    split_kernel<<<NL * (int)(DFD >> 11), 256>>>(Wfc, pwfch, pwfcl, 22, DFD);
    split_kernel<<<NL * (int)(DFD >> 11), 256>>>(Wp,  pwph,  pwpl,  22, DFD);

    scan_kernel<<<1, S>>>(levels, pcpad);
    mask_kernel<<<(S * S) / 256, 256>>>(levels, sidx, pcpad, pmask);
    ropetab_kernel<<<S, 32>>>(pcos, psin);
    rms_dual_kernel<<<S, 256>>>(x, px, px0);

    for (int i = 0; i < NL; i++) {
        prelayer_kernel<<<S, 256>>>(px, px0, lambdas, i, pxl, pxnh, pxnl);

        // fused QKV: [1024 x 3072], 384 tiles of 64x128
        mma_gemm<64,128,0><<<dim3(3 * D / 128, S / 64), 256, SMEM_6412>>>(
            pxnh, pxnl, pwqkvh + (size_t)i * 3 * DD, pwqkvl + (size_t)i * 3 * DD,
            pq, pk, pv, nullptr, nullptr, nullptr, D, D);

        qkvprep_kernel<<<dim3(S, 4), 128>>>(pq, pk, pv, pv1, lamb, i, pcos, psin,
                                            pqh, pql, pkh, pkl, pvh, pvl);

        attn_mma_kernel<<<dim3(S / 64, H), 128, SMEMATT>>>(
            pqh, pql, pkh, pkl, pvh, pvl, pyh, pyl, pmask);

        // x = xl + y @ Wo^T : 256 tiles of 64x64
        mma_gemm<64,64,1><<<dim3(D / 64, S / 64), 256, SMEM_6464>>>(
            pyh, pyl, pwoh + (size_t)i * DD, pwol + (size_t)i * DD,
            px, nullptr, nullptr, pxl, nullptr, nullptr, D, D);

        // h = relu(rms(x) @ Wfc^T)^2 : 512 tiles of 64x128
        rms_split_kernel<<<S, 256>>>(px, pxnh, pxnl);
        mma_gemm<64,128,2><<<dim3(DFF / 128, S / 64), 256, SMEM_6412>>>(
            pxnh, pxnl, pwfch + (size_t)i * DFD, pwfcl + (size_t)i * DFD,
            nullptr, nullptr, nullptr, nullptr, phh, phl, D, DFF);

        // x = x + h @ Wp^T : 256 tiles of 64x64, K=4096
        mma_gemm<64,64,1><<<dim3(D / 64, S / 64), 256, SMEM_6464>>>(
            phh, phl, pwph + (size_t)i * DFD, pwpl + (size_t)i * DFD,
            px, nullptr, nullptr, px, nullptr, nullptr, DFF, D);
    }

    rms_dual_kernel<<<S, 256>>>(px, out, nullptr);
}